// round 12
// baseline (speedup 1.0000x reference)
#include <cuda_runtime.h>
#include <cuda_bf16.h>
#include <cstdint>
#include <cstddef>

#define B_TOT 1024
#define NTOK  98
#define DIM   192
#define HEADS 6
#define HD    32
#define NW    64
#define TABLE 507
#define MTOT  (B_TOT * NTOK)

__device__ float g_kv [ (size_t)B_TOT * NTOK * 2 * DIM ];
__device__ float g_ctx[ (size_t)B_TOT * NTOK * DIM ];
__device__ __nv_bfloat16 g_w3kv[(size_t)576 * 384];
__device__ __nv_bfloat16 g_w3pj[(size_t)576 * 192];
__device__ float g_cbias[(size_t)NW * HEADS * NTOK * NTOK];

// ======================= helpers ===========================================
__device__ __forceinline__ uint32_t smem_u32(const void* p) {
    uint32_t a;
    asm("{ .reg .u64 t; cvta.to.shared.u64 t, %1; cvt.u32.u64 %0, t; }"
        : "=r"(a) : "l"(p));
    return a;
}
__device__ __forceinline__ void ldsm4(uint32_t addr, uint32_t* r) {
    asm volatile("ldmatrix.sync.aligned.m8n8.x4.shared.b16 {%0,%1,%2,%3}, [%4];"
        : "=r"(r[0]), "=r"(r[1]), "=r"(r[2]), "=r"(r[3]) : "r"(addr));
}
__device__ __forceinline__ void ldsm4t(uint32_t addr, uint32_t* r) {
    asm volatile("ldmatrix.sync.aligned.m8n8.x4.trans.shared.b16 {%0,%1,%2,%3}, [%4];"
        : "=r"(r[0]), "=r"(r[1]), "=r"(r[2]), "=r"(r[3]) : "r"(addr));
}
__device__ __forceinline__ void mma16816(float* c, const uint32_t* a,
                                         uint32_t b0, uint32_t b1) {
    asm volatile("mma.sync.aligned.m16n8k16.row.col.f32.bf16.bf16.f32 "
        "{%0,%1,%2,%3}, {%4,%5,%6,%7}, {%8,%9}, {%0,%1,%2,%3};"
        : "+f"(c[0]), "+f"(c[1]), "+f"(c[2]), "+f"(c[3])
        : "r"(a[0]), "r"(a[1]), "r"(a[2]), "r"(a[3]), "r"(b0), "r"(b1));
}
__device__ __forceinline__ uint32_t packbf(float lo, float hi) {
    uint32_t r;
    asm("cvt.rn.bf16x2.f32 %0, %1, %2;" : "=r"(r) : "f"(hi), "f"(lo));
    return r;
}

// ======================= precompute kernels ================================
__global__ void build_w3t(const float* __restrict__ W, __nv_bfloat16* __restrict__ w3t, int N)
{
    int idx = blockIdx.x * 256 + threadIdx.x;
    if (idx >= 192 * N) return;
    int k = idx / N, n = idx % N;
    float a = W[idx];
    __nv_bfloat16 hi = __float2bfloat16_rn(a);
    __nv_bfloat16 lo = __float2bfloat16_rn(a - __bfloat162float(hi));
    w3t[(size_t)k * N + n]         = hi;
    w3t[(size_t)(192 + k) * N + n] = lo;
    w3t[(size_t)(384 + k) * N + n] = hi;
}

__global__ void build_cbias(const float* __restrict__ mask,
                            const float* __restrict__ rpb,
                            const int*   __restrict__ rel_idx,
                            float* __restrict__ cb)
{
    int idx = blockIdx.x * 256 + threadIdx.x;
    if (idx >= NW * HEADS * NTOK * NTOK) return;
    int k = idx % NTOK;
    int t = idx / NTOK;
    int q = t % NTOK;  t /= NTOK;
    int h = t % HEADS; int w = t / HEADS;
    cb[idx] = mask[((size_t)w * NTOK + q) * NTOK + k] +
              rpb[(size_t)rel_idx[q * NTOK + k] * HEADS + h];
}

// ======================= GEMM v4: BM=64, 3 CTAs/SM =========================
template<int BN>
__global__ __launch_bounds__(256, 3) void gemm_mma64(
    const float* __restrict__ A,
    const __nv_bfloat16* __restrict__ W3T,   // [576][N]
    const float* __restrict__ bias,
    float* __restrict__ C, int N)
{
    constexpr int SB  = BN + 8;
    constexpr int NFR = BN / 16;              // warp n frags (warp tile 16 x BN/2)
    __shared__ __align__(16) __nv_bfloat16 As[64][72];
    __shared__ __align__(16) __nv_bfloat16 Bs[64][SB];

    const int tid  = threadIdx.x;
    const int lane = tid & 31;
    const int w    = tid >> 5;
    const size_t bm = (size_t)blockIdx.y * 64;
    const int    bn = blockIdx.x * BN;
    const int m0 = (w & 3) * 16, n0 = (w >> 2) * (BN / 2);

    const uint32_t qrow = lane & 15;
    const uint32_t a_base = smem_u32(As) + ((qrow + m0) * 72 + (lane >> 4) * 8) * 2;
    const uint32_t b_base = smem_u32(Bs) + (qrow * SB + n0 + (lane >> 4) * 8) * 2;

    float acc[NFR][4] = {};

    const int sched[9] = {0, 3, 1, 4, 2, 5, 6, 7, 8};
    #pragma unroll 1
    for (int s = 0; s < 9; s++) {
        const int c = sched[s];
        const bool newA = !(s == 1 || s == 3 || s == 5);
        __syncthreads();
        if (newA) {
            const int  k0     = (c % 3) * 64;
            const bool use_lo = (c >= 6);
            #pragma unroll
            for (int o = tid; o < 512; o += 256) {
                int row = o >> 3, cg = (o & 7) * 8;
                const float* ap = &A[(bm + row) * 192 + k0 + cg];
                float4 f0 = *(const float4*)ap;
                float4 f1 = *(const float4*)(ap + 4);
                float v[8] = {f0.x, f0.y, f0.z, f0.w, f1.x, f1.y, f1.z, f1.w};
                union { __nv_bfloat16 hh[8]; uint4 u; } pk;
                #pragma unroll
                for (int i = 0; i < 8; i++) {
                    __nv_bfloat16 hi = __float2bfloat16_rn(v[i]);
                    pk.hh[i] = use_lo ? __float2bfloat16_rn(v[i] - __bfloat162float(hi)) : hi;
                }
                *(uint4*)&As[row][cg] = pk.u;
            }
        }
        #pragma unroll
        for (int o = tid; o < 64 * (BN / 8); o += 256) {
            int kk = o / (BN / 8), cg = (o % (BN / 8)) * 8;
            *(uint4*)&Bs[kk][cg] =
                *(const uint4*)&W3T[(size_t)(c * 64 + kk) * N + bn + cg];
        }
        __syncthreads();

        #pragma unroll
        for (int ks = 0; ks < 4; ks++) {
            uint32_t a[4];
            ldsm4(a_base + (uint32_t)(ks * 16 * 2), a);
            #pragma unroll
            for (int nb = 0; nb < NFR / 2; nb++) {
                uint32_t bq[4];
                ldsm4t(b_base + (uint32_t)((ks * 16 * SB + nb * 16) * 2), bq);
                mma16816(acc[2 * nb],     a, bq[0], bq[1]);
                mma16816(acc[2 * nb + 1], a, bq[2], bq[3]);
            }
        }
    }

    const size_t row0 = bm + m0 + (lane >> 2);
    #pragma unroll
    for (int ni = 0; ni < NFR; ni++) {
        const int col = bn + n0 + ni * 8 + 2 * (lane & 3);
        float2 bv = *(const float2*)&bias[col];
        *(float2*)&C[row0 * N + col] =
            make_float2(acc[ni][0] + bv.x, acc[ni][1] + bv.y);
        *(float2*)&C[(row0 + 8) * N + col] =
            make_float2(acc[ni][2] + bv.x, acc[ni][3] + bv.y);
    }
}

// ======================= attention v3.1 (R11, measured-good) ===============
__global__ __launch_bounds__(224, 3) void attn_mma2(
    const float* __restrict__ x_up,
    const float* __restrict__ kv,
    const float* __restrict__ cbias,
    float*       __restrict__ ctx)
{
    const int h = blockIdx.x;
    const int b = blockIdx.y;

    extern __shared__ __align__(16) char smem[];
    __nv_bfloat16* QH = (__nv_bfloat16*)smem;          // [112][40]
    __nv_bfloat16* QL = QH + 112 * 40;
    __nv_bfloat16* KH = QL + 112 * 40;                 // [112][40]
    __nv_bfloat16* KL = KH + 112 * 40;
    __nv_bfloat16* VH = KL + 112 * 40;                 // [112][40]
    __nv_bfloat16* VL = VH + 112 * 40;

    const int tid  = threadIdx.x;
    const int lane = tid & 31;
    const int w    = tid >> 5;
    const float scale = 0.1767766952966369f;

    const float* xb  = x_up + ((size_t)b * NTOK) * DIM + h * HD;
    const float* kvb = kv + (size_t)b * NTOK * 384;

    #pragma unroll
    for (int o = tid; o < 896; o += 224) {
        int row = o >> 3, c4 = (o & 7) * 4;
        uint2 qh = {0, 0}, ql = {0, 0}, kh = {0, 0}, kl = {0, 0}, vh = {0, 0}, vl = {0, 0};
        if (row < NTOK) {
            float4 fq = *(const float4*)(xb + (size_t)row * DIM + c4);
            float4 fk = *(const float4*)(kvb + (size_t)row * 384 + h * HD + c4);
            float4 fv = *(const float4*)(kvb + (size_t)row * 384 + DIM + h * HD + c4);
            float vq[4] = {fq.x * scale, fq.y * scale, fq.z * scale, fq.w * scale};
            float vk[4] = {fk.x, fk.y, fk.z, fk.w};
            float vv[4] = {fv.x, fv.y, fv.z, fv.w};
            union { __nv_bfloat16 h2[4]; uint2 u; } t0, t1;
            #pragma unroll
            for (int i = 0; i < 4; i++) {
                __nv_bfloat16 hi = __float2bfloat16_rn(vq[i]);
                t0.h2[i] = hi;
                t1.h2[i] = __float2bfloat16_rn(vq[i] - __bfloat162float(hi));
            }
            qh = t0.u; ql = t1.u;
            #pragma unroll
            for (int i = 0; i < 4; i++) {
                __nv_bfloat16 hi = __float2bfloat16_rn(vk[i]);
                t0.h2[i] = hi;
                t1.h2[i] = __float2bfloat16_rn(vk[i] - __bfloat162float(hi));
            }
            kh = t0.u; kl = t1.u;
            #pragma unroll
            for (int i = 0; i < 4; i++) {
                __nv_bfloat16 hi = __float2bfloat16_rn(vv[i]);
                t0.h2[i] = hi;
                t1.h2[i] = __float2bfloat16_rn(vv[i] - __bfloat162float(hi));
            }
            vh = t0.u; vl = t1.u;
        }
        *(uint2*)(QH + row * 40 + c4) = qh;
        *(uint2*)(QL + row * 40 + c4) = ql;
        *(uint2*)(KH + row * 40 + c4) = kh;
        *(uint2*)(KL + row * 40 + c4) = kl;
        *(uint2*)(VH + row * 40 + c4) = vh;
        *(uint2*)(VL + row * 40 + c4) = vl;
    }
    __syncthreads();

    const int m0 = w * 16;
    const uint32_t qrow = lane & 15;
    const uint32_t acol = (lane >> 4) * 8;
    const uint32_t aQH = smem_u32(QH) + ((m0 + qrow) * 40 + acol) * 2;
    const uint32_t aQL = aQH + 112 * 40 * 2;
    const uint32_t bKH = smem_u32(KH) + (qrow * 40 + acol) * 2;
    const uint32_t bKL = bKH + 112 * 40 * 2;

    float acc[14][4] = {};
    #pragma unroll
    for (int k16 = 0; k16 < 2; k16++) {
        uint32_t ah[4], al[4];
        ldsm4(aQH + (uint32_t)(k16 * 32), ah);
        ldsm4(aQL + (uint32_t)(k16 * 32), al);
        #pragma unroll
        for (int jt = 0; jt < 7; jt++) {
            uint32_t bh[4], bl[4];
            ldsm4(bKH + (uint32_t)((jt * 16 * 40 + k16 * 16) * 2), bh);
            ldsm4(bKL + (uint32_t)((jt * 16 * 40 + k16 * 16) * 2), bl);
            mma16816(acc[2 * jt],     ah, bh[0], bh[2]);
            mma16816(acc[2 * jt + 1], ah, bh[1], bh[3]);
            mma16816(acc[2 * jt],     al, bh[0], bh[2]);
            mma16816(acc[2 * jt + 1], al, bh[1], bh[3]);
            mma16816(acc[2 * jt],     ah, bl[0], bl[2]);
            mma16816(acc[2 * jt + 1], ah, bl[1], bl[3]);
        }
    }

    const int ra = m0 + (lane >> 2), rb = ra + 8;
    const bool okA = ra < NTOK, okB = rb < NTOK;
    const float* cbq = cbias + (((size_t)(b & (NW - 1)) * HEADS + h) * NTOK) * NTOK;
    const float* pA = cbq + (size_t)ra * NTOK;
    const float* pB = cbq + (size_t)rb * NTOK;
    float sA = 0.f, sB = 0.f;
    #pragma unroll
    for (int ni = 0; ni < 14; ni++) {
        const int c0 = ni * 8 + 2 * (lane & 3);
        const bool okC = c0 < NTOK;
        float e0 = 0.f, e1 = 0.f, e2 = 0.f, e3 = 0.f;
        if (okA && okC) {
            float2 cb = *(const float2*)(pA + c0);
            e0 = __expf(acc[ni][0] + cb.x);
            e1 = __expf(acc[ni][1] + cb.y);
        }
        if (okB && okC) {
            float2 cb = *(const float2*)(pB + c0);
            e2 = __expf(acc[ni][2] + cb.x);
            e3 = __expf(acc[ni][3] + cb.y);
        }
        sA += e0 + e1; sB += e2 + e3;
        acc[ni][0] = e0; acc[ni][1] = e1;
        acc[ni][2] = e2; acc[ni][3] = e3;
    }
    sA += __shfl_xor_sync(0xffffffffu, sA, 1);
    sA += __shfl_xor_sync(0xffffffffu, sA, 2);
    sB += __shfl_xor_sync(0xffffffffu, sB, 1);
    sB += __shfl_xor_sync(0xffffffffu, sB, 2);
    const float invA = 1.f / sA, invB = 1.f / sB;

    float o[4][4] = {};
    const uint32_t bVH = smem_u32(VH) + (qrow * 40 + acol) * 2;
    const uint32_t bVL = bVH + 112 * 40 * 2;
    #pragma unroll
    for (int kt = 0; kt < 7; kt++) {
        const float* cA = acc[2 * kt];
        const float* cB = acc[2 * kt + 1];
        uint32_t ph[4], pl[4];
        ph[0] = packbf(cA[0], cA[1]);
        ph[1] = packbf(cA[2], cA[3]);
        ph[2] = packbf(cB[0], cB[1]);
        ph[3] = packbf(cB[2], cB[3]);
        pl[0] = packbf(cA[0] - __uint_as_float(ph[0] << 16),
                       cA[1] - __uint_as_float(ph[0] & 0xFFFF0000u));
        pl[1] = packbf(cA[2] - __uint_as_float(ph[1] << 16),
                       cA[3] - __uint_as_float(ph[1] & 0xFFFF0000u));
        pl[2] = packbf(cB[0] - __uint_as_float(ph[2] << 16),
                       cB[1] - __uint_as_float(ph[2] & 0xFFFF0000u));
        pl[3] = packbf(cB[2] - __uint_as_float(ph[3] << 16),
                       cB[3] - __uint_as_float(ph[3] & 0xFFFF0000u));

        uint32_t vh0[4], vh1[4], vl0[4], vl1[4];
        ldsm4t(bVH + (uint32_t)(kt * 16 * 40 * 2),        vh0);
        ldsm4t(bVH + (uint32_t)((kt * 16 * 40 + 16) * 2), vh1);
        ldsm4t(bVL + (uint32_t)(kt * 16 * 40 * 2),        vl0);
        ldsm4t(bVL + (uint32_t)((kt * 16 * 40 + 16) * 2), vl1);

        mma16816(o[0], ph, vh0[0], vh0[1]);
        mma16816(o[1], ph, vh0[2], vh0[3]);
        mma16816(o[2], ph, vh1[0], vh1[1]);
        mma16816(o[3], ph, vh1[2], vh1[3]);
        mma16816(o[0], pl, vh0[0], vh0[1]);
        mma16816(o[1], pl, vh0[2], vh0[3]);
        mma16816(o[2], pl, vh1[0], vh1[1]);
        mma16816(o[3], pl, vh1[2], vh1[3]);
        mma16816(o[0], ph, vl0[0], vl0[1]);
        mma16816(o[1], ph, vl0[2], vl0[3]);
        mma16816(o[2], ph, vl1[0], vl1[1]);
        mma16816(o[3], ph, vl1[2], vl1[3]);
    }

    #pragma unroll
    for (int vn = 0; vn < 4; vn++) {
        const int col = h * HD + vn * 8 + 2 * (lane & 3);
        if (okA)
            *(float2*)(ctx + ((size_t)b * NTOK + ra) * DIM + col) =
                make_float2(o[vn][0] * invA, o[vn][1] * invA);
        if (okB)
            *(float2*)(ctx + ((size_t)b * NTOK + rb) * DIM + col) =
                make_float2(o[vn][2] * invB, o[vn][3] * invB);
    }
}

// ---------------------------------------------------------------------------
extern "C" void kernel_launch(void* const* d_in, const int* in_sizes, int n_in,
                              void* d_out, int out_size)
{
    const float* skip    = (const float*)d_in[0];
    const float* x_up    = (const float*)d_in[1];
    const float* mask    = (const float*)d_in[2];
    const float* kv_w    = (const float*)d_in[3];
    const float* kv_b    = (const float*)d_in[4];
    const float* proj_w  = (const float*)d_in[5];
    const float* proj_b  = (const float*)d_in[6];
    const float* rpb     = (const float*)d_in[7];
    const int*   rel_idx = (const int*)  d_in[8];
    float* out = (float*)d_out;

    float *kvbuf = nullptr, *ctxbuf = nullptr, *cbbuf = nullptr;
    __nv_bfloat16 *w3kv = nullptr, *w3pj = nullptr;
    cudaGetSymbolAddress((void**)&kvbuf,  g_kv);
    cudaGetSymbolAddress((void**)&ctxbuf, g_ctx);
    cudaGetSymbolAddress((void**)&w3kv,   g_w3kv);
    cudaGetSymbolAddress((void**)&w3pj,   g_w3pj);
    cudaGetSymbolAddress((void**)&cbbuf,  g_cbias);

    const int ATTN_SMEM = 6 * 112 * 40 * 2;   // 53760
    cudaFuncSetAttribute(attn_mma2, cudaFuncAttributeMaxDynamicSharedMemorySize, ATTN_SMEM);

    // #1: kv weight split
    build_w3t<<<(192 * 384 + 255) / 256, 256>>>(kv_w, w3kv, 384);
    // #2: kv = split3(skip) @ w3kv + kv_b
    {
        dim3 grid(384 / 128, MTOT / 64);
        gemm_mma64<128><<<grid, 256>>>(skip, w3kv, kv_b, kvbuf, 384);
    }
    // #3: combined bias
    build_cbias<<<(NW * HEADS * NTOK * NTOK + 255) / 256, 256>>>(mask, rpb, rel_idx, cbbuf);
    // #4: attention
    {
        dim3 grid(HEADS, B_TOT);
        attn_mma2<<<grid, 224, ATTN_SMEM>>>(x_up, kvbuf, cbbuf, ctxbuf);
    }
    // #5: proj weight split
    build_w3t<<<(192 * 192 + 255) / 256, 256>>>(proj_w, w3pj, 192);
    // #6: out = split3(ctx) @ w3pj + proj_b
    {
        dim3 grid(192 / 96, MTOT / 64);
        gemm_mma64<96><<<grid, 256>>>(ctxbuf, w3pj, proj_b, out, 192);
    }
}

// round 13
// speedup vs baseline: 1.0213x; 1.0213x over previous
#include <cuda_runtime.h>
#include <cuda_bf16.h>
#include <cstdint>
#include <cstddef>

#define B_TOT 1024
#define NTOK  98
#define DIM   192
#define HEADS 6
#define HD    32
#define NW    64
#define TABLE 507
#define MTOT  (B_TOT * NTOK)

__device__ float g_kv [ (size_t)B_TOT * NTOK * 2 * DIM ];
__device__ float g_ctx[ (size_t)B_TOT * NTOK * DIM ];
__device__ __nv_bfloat16 g_w3kv[(size_t)576 * 384];
__device__ __nv_bfloat16 g_w3pj[(size_t)576 * 192];
__device__ float g_cbias[(size_t)NW * HEADS * NTOK * NTOK];

// ======================= helpers ===========================================
__device__ __forceinline__ uint32_t smem_u32(const void* p) {
    uint32_t a;
    asm("{ .reg .u64 t; cvta.to.shared.u64 t, %1; cvt.u32.u64 %0, t; }"
        : "=r"(a) : "l"(p));
    return a;
}
__device__ __forceinline__ void ldsm4(uint32_t addr, uint32_t* r) {
    asm volatile("ldmatrix.sync.aligned.m8n8.x4.shared.b16 {%0,%1,%2,%3}, [%4];"
        : "=r"(r[0]), "=r"(r[1]), "=r"(r[2]), "=r"(r[3]) : "r"(addr));
}
__device__ __forceinline__ void ldsm4t(uint32_t addr, uint32_t* r) {
    asm volatile("ldmatrix.sync.aligned.m8n8.x4.trans.shared.b16 {%0,%1,%2,%3}, [%4];"
        : "=r"(r[0]), "=r"(r[1]), "=r"(r[2]), "=r"(r[3]) : "r"(addr));
}
__device__ __forceinline__ void mma16816(float* c, const uint32_t* a,
                                         uint32_t b0, uint32_t b1) {
    asm volatile("mma.sync.aligned.m16n8k16.row.col.f32.bf16.bf16.f32 "
        "{%0,%1,%2,%3}, {%4,%5,%6,%7}, {%8,%9}, {%0,%1,%2,%3};"
        : "+f"(c[0]), "+f"(c[1]), "+f"(c[2]), "+f"(c[3])
        : "r"(a[0]), "r"(a[1]), "r"(a[2]), "r"(a[3]), "r"(b0), "r"(b1));
}
__device__ __forceinline__ uint32_t packbf(float lo, float hi) {
    uint32_t r;
    asm("cvt.rn.bf16x2.f32 %0, %1, %2;" : "=r"(r) : "f"(hi), "f"(lo));
    return r;
}

// ======================= precompute kernels ================================
__global__ void build_w3t(const float* __restrict__ W, __nv_bfloat16* __restrict__ w3t, int N)
{
    int idx = blockIdx.x * 256 + threadIdx.x;
    if (idx >= 192 * N) return;
    int k = idx / N, n = idx % N;
    float a = W[idx];
    __nv_bfloat16 hi = __float2bfloat16_rn(a);
    __nv_bfloat16 lo = __float2bfloat16_rn(a - __bfloat162float(hi));
    w3t[(size_t)k * N + n]         = hi;
    w3t[(size_t)(192 + k) * N + n] = lo;
    w3t[(size_t)(384 + k) * N + n] = hi;
}

__global__ void build_cbias(const float* __restrict__ mask,
                            const float* __restrict__ rpb,
                            const int*   __restrict__ rel_idx,
                            float* __restrict__ cb)
{
    int idx = blockIdx.x * 256 + threadIdx.x;
    if (idx >= NW * HEADS * NTOK * NTOK) return;
    int k = idx % NTOK;
    int t = idx / NTOK;
    int q = t % NTOK;  t /= NTOK;
    int h = t % HEADS; int w = t / HEADS;
    cb[idx] = mask[((size_t)w * NTOK + q) * NTOK + k] +
              rpb[(size_t)rel_idx[q * NTOK + k] * HEADS + h];
}

// ======================= R6 mma.sync GEMM (BM=128, measured-good) ==========
template<int BN>
__global__ __launch_bounds__(256) void gemm_mma(
    const float* __restrict__ A,
    const __nv_bfloat16* __restrict__ W3T,   // [576][N]
    const float* __restrict__ bias,
    float* __restrict__ C, int N)
{
    constexpr int SB  = BN + 8;
    constexpr int NFR = BN / 16;
    __shared__ __align__(16) __nv_bfloat16 As[128][72];
    __shared__ __align__(16) __nv_bfloat16 Bs[64][SB];

    const int tid  = threadIdx.x;
    const int lane = tid & 31;
    const int w    = tid >> 5;
    const size_t bm = (size_t)blockIdx.y * 128;
    const int    bn = blockIdx.x * BN;
    const int m0 = (w & 3) * 32, n0 = (w >> 2) * (BN / 2);

    const uint32_t qrow = lane & 15;
    const uint32_t a_base = smem_u32(As) + ((qrow + m0) * 72 + (lane >> 4) * 8) * 2;
    const uint32_t b_base = smem_u32(Bs) + (qrow * SB + n0 + (lane >> 4) * 8) * 2;

    float acc[2][NFR][4] = {};

    const int sched[9] = {0, 3, 1, 4, 2, 5, 6, 7, 8};
    #pragma unroll 1
    for (int s = 0; s < 9; s++) {
        const int c = sched[s];
        const bool newA = !(s == 1 || s == 3 || s == 5);
        __syncthreads();
        if (newA) {
            const int  k0     = (c % 3) * 64;
            const bool use_lo = (c >= 6);
            #pragma unroll
            for (int o = tid; o < 1024; o += 256) {
                int row = o >> 3, cg = (o & 7) * 8;
                const float* ap = &A[(bm + row) * 192 + k0 + cg];
                float4 f0 = *(const float4*)ap;
                float4 f1 = *(const float4*)(ap + 4);
                float v[8] = {f0.x, f0.y, f0.z, f0.w, f1.x, f1.y, f1.z, f1.w};
                union { __nv_bfloat16 hh[8]; uint4 u; } pk;
                #pragma unroll
                for (int i = 0; i < 8; i++) {
                    __nv_bfloat16 hi = __float2bfloat16_rn(v[i]);
                    pk.hh[i] = use_lo ? __float2bfloat16_rn(v[i] - __bfloat162float(hi)) : hi;
                }
                *(uint4*)&As[row][cg] = pk.u;
            }
        }
        #pragma unroll
        for (int o = tid; o < 64 * (BN / 8); o += 256) {
            int kk = o / (BN / 8), cg = (o % (BN / 8)) * 8;
            *(uint4*)&Bs[kk][cg] =
                *(const uint4*)&W3T[(size_t)(c * 64 + kk) * N + bn + cg];
        }
        __syncthreads();

        #pragma unroll
        for (int ks = 0; ks < 4; ks++) {
            uint32_t a[2][4];
            ldsm4(a_base + (uint32_t)(ks * 16 * 2),             a[0]);
            ldsm4(a_base + (uint32_t)((16 * 72 + ks * 16) * 2), a[1]);
            #pragma unroll
            for (int nb = 0; nb < NFR / 2; nb++) {
                uint32_t bq[4];
                ldsm4t(b_base + (uint32_t)((ks * 16 * SB + nb * 16) * 2), bq);
                #pragma unroll
                for (int mi = 0; mi < 2; mi++) {
                    mma16816(acc[mi][2 * nb],     a[mi], bq[0], bq[1]);
                    mma16816(acc[mi][2 * nb + 1], a[mi], bq[2], bq[3]);
                }
            }
        }
    }

    #pragma unroll
    for (int mi = 0; mi < 2; mi++) {
        const size_t row0 = bm + m0 + mi * 16 + (lane >> 2);
        #pragma unroll
        for (int ni = 0; ni < NFR; ni++) {
            const int col = bn + n0 + ni * 8 + 2 * (lane & 3);
            float2 bv = *(const float2*)&bias[col];
            *(float2*)&C[row0 * N + col] =
                make_float2(acc[mi][ni][0] + bv.x, acc[mi][ni][1] + bv.y);
            *(float2*)&C[(row0 + 8) * N + col] =
                make_float2(acc[mi][ni][2] + bv.x, acc[mi][ni][3] + bv.y);
        }
    }
}

// ======================= attention v3.2: 4 CTAs/SM target ==================
__global__ __launch_bounds__(224, 4) void attn_mma2(
    const float* __restrict__ x_up,
    const float* __restrict__ kv,
    const float* __restrict__ cbias,
    float*       __restrict__ ctx)
{
    const int h = blockIdx.x;
    const int b = blockIdx.y;

    extern __shared__ __align__(16) char smem[];
    __nv_bfloat16* QH = (__nv_bfloat16*)smem;          // [112][40]
    __nv_bfloat16* QL = QH + 112 * 40;
    __nv_bfloat16* KH = QL + 112 * 40;                 // [112][40]
    __nv_bfloat16* KL = KH + 112 * 40;
    __nv_bfloat16* VH = KL + 112 * 40;                 // [112][40]
    __nv_bfloat16* VL = VH + 112 * 40;

    const int tid  = threadIdx.x;
    const int lane = tid & 31;
    const int w    = tid >> 5;
    const float scale = 0.1767766952966369f;

    const float* xb  = x_up + ((size_t)b * NTOK) * DIM + h * HD;
    const float* kvb = kv + (size_t)b * NTOK * 384;

    #pragma unroll
    for (int o = tid; o < 896; o += 224) {
        int row = o >> 3, c4 = (o & 7) * 4;
        uint2 qh = {0, 0}, ql = {0, 0}, kh = {0, 0}, kl = {0, 0}, vh = {0, 0}, vl = {0, 0};
        if (row < NTOK) {
            float4 fq = *(const float4*)(xb + (size_t)row * DIM + c4);
            float4 fk = *(const float4*)(kvb + (size_t)row * 384 + h * HD + c4);
            float4 fv = *(const float4*)(kvb + (size_t)row * 384 + DIM + h * HD + c4);
            float vq[4] = {fq.x * scale, fq.y * scale, fq.z * scale, fq.w * scale};
            float vk[4] = {fk.x, fk.y, fk.z, fk.w};
            float vv[4] = {fv.x, fv.y, fv.z, fv.w};
            union { __nv_bfloat16 h2[4]; uint2 u; } t0, t1;
            #pragma unroll
            for (int i = 0; i < 4; i++) {
                __nv_bfloat16 hi = __float2bfloat16_rn(vq[i]);
                t0.h2[i] = hi;
                t1.h2[i] = __float2bfloat16_rn(vq[i] - __bfloat162float(hi));
            }
            qh = t0.u; ql = t1.u;
            #pragma unroll
            for (int i = 0; i < 4; i++) {
                __nv_bfloat16 hi = __float2bfloat16_rn(vk[i]);
                t0.h2[i] = hi;
                t1.h2[i] = __float2bfloat16_rn(vk[i] - __bfloat162float(hi));
            }
            kh = t0.u; kl = t1.u;
            #pragma unroll
            for (int i = 0; i < 4; i++) {
                __nv_bfloat16 hi = __float2bfloat16_rn(vv[i]);
                t0.h2[i] = hi;
                t1.h2[i] = __float2bfloat16_rn(vv[i] - __bfloat162float(hi));
            }
            vh = t0.u; vl = t1.u;
        }
        *(uint2*)(QH + row * 40 + c4) = qh;
        *(uint2*)(QL + row * 40 + c4) = ql;
        *(uint2*)(KH + row * 40 + c4) = kh;
        *(uint2*)(KL + row * 40 + c4) = kl;
        *(uint2*)(VH + row * 40 + c4) = vh;
        *(uint2*)(VL + row * 40 + c4) = vl;
    }
    __syncthreads();

    const int m0 = w * 16;
    const uint32_t qrow = lane & 15;
    const uint32_t acol = (lane >> 4) * 8;
    const uint32_t aQH = smem_u32(QH) + ((m0 + qrow) * 40 + acol) * 2;
    const uint32_t aQL = aQH + 112 * 40 * 2;
    const uint32_t bKH = smem_u32(KH) + (qrow * 40 + acol) * 2;
    const uint32_t bKL = bKH + 112 * 40 * 2;

    float acc[14][4] = {};
    #pragma unroll
    for (int k16 = 0; k16 < 2; k16++) {
        uint32_t ah[4], al[4];
        ldsm4(aQH + (uint32_t)(k16 * 32), ah);
        ldsm4(aQL + (uint32_t)(k16 * 32), al);
        #pragma unroll
        for (int jt = 0; jt < 7; jt++) {
            uint32_t bh[4], bl[4];
            ldsm4(bKH + (uint32_t)((jt * 16 * 40 + k16 * 16) * 2), bh);
            ldsm4(bKL + (uint32_t)((jt * 16 * 40 + k16 * 16) * 2), bl);
            mma16816(acc[2 * jt],     ah, bh[0], bh[2]);
            mma16816(acc[2 * jt + 1], ah, bh[1], bh[3]);
            mma16816(acc[2 * jt],     al, bh[0], bh[2]);
            mma16816(acc[2 * jt + 1], al, bh[1], bh[3]);
            mma16816(acc[2 * jt],     ah, bl[0], bl[2]);
            mma16816(acc[2 * jt + 1], ah, bl[1], bl[3]);
        }
    }

    const int ra = m0 + (lane >> 2), rb = ra + 8;
    const bool okA = ra < NTOK, okB = rb < NTOK;
    const float* cbq = cbias + (((size_t)(b & (NW - 1)) * HEADS + h) * NTOK) * NTOK;
    const float* pA = cbq + (size_t)ra * NTOK;
    const float* pB = cbq + (size_t)rb * NTOK;
    float sA = 0.f, sB = 0.f;
    #pragma unroll
    for (int ni = 0; ni < 14; ni++) {
        const int c0 = ni * 8 + 2 * (lane & 3);
        const bool okC = c0 < NTOK;
        float e0 = 0.f, e1 = 0.f, e2 = 0.f, e3 = 0.f;
        if (okA && okC) {
            float2 cb = *(const float2*)(pA + c0);
            e0 = __expf(acc[ni][0] + cb.x);
            e1 = __expf(acc[ni][1] + cb.y);
        }
        if (okB && okC) {
            float2 cb = *(const float2*)(pB + c0);
            e2 = __expf(acc[ni][2] + cb.x);
            e3 = __expf(acc[ni][3] + cb.y);
        }
        sA += e0 + e1; sB += e2 + e3;
        acc[ni][0] = e0; acc[ni][1] = e1;
        acc[ni][2] = e2; acc[ni][3] = e3;
    }
    sA += __shfl_xor_sync(0xffffffffu, sA, 1);
    sA += __shfl_xor_sync(0xffffffffu, sA, 2);
    sB += __shfl_xor_sync(0xffffffffu, sB, 1);
    sB += __shfl_xor_sync(0xffffffffu, sB, 2);
    const float invA = 1.f / sA, invB = 1.f / sB;

    float o[4][4] = {};
    const uint32_t bVH = smem_u32(VH) + (qrow * 40 + acol) * 2;
    const uint32_t bVL = bVH + 112 * 40 * 2;
    #pragma unroll
    for (int kt = 0; kt < 7; kt++) {
        const float* cA = acc[2 * kt];
        const float* cB = acc[2 * kt + 1];
        uint32_t ph[4], pl[4];
        ph[0] = packbf(cA[0], cA[1]);
        ph[1] = packbf(cA[2], cA[3]);
        ph[2] = packbf(cB[0], cB[1]);
        ph[3] = packbf(cB[2], cB[3]);
        pl[0] = packbf(cA[0] - __uint_as_float(ph[0] << 16),
                       cA[1] - __uint_as_float(ph[0] & 0xFFFF0000u));
        pl[1] = packbf(cA[2] - __uint_as_float(ph[1] << 16),
                       cA[3] - __uint_as_float(ph[1] & 0xFFFF0000u));
        pl[2] = packbf(cB[0] - __uint_as_float(ph[2] << 16),
                       cB[1] - __uint_as_float(ph[2] & 0xFFFF0000u));
        pl[3] = packbf(cB[2] - __uint_as_float(ph[3] << 16),
                       cB[3] - __uint_as_float(ph[3] & 0xFFFF0000u));

        uint32_t vh0[4], vh1[4], vl0[4], vl1[4];
        ldsm4t(bVH + (uint32_t)(kt * 16 * 40 * 2),        vh0);
        ldsm4t(bVH + (uint32_t)((kt * 16 * 40 + 16) * 2), vh1);
        ldsm4t(bVL + (uint32_t)(kt * 16 * 40 * 2),        vl0);
        ldsm4t(bVL + (uint32_t)((kt * 16 * 40 + 16) * 2), vl1);

        mma16816(o[0], ph, vh0[0], vh0[1]);
        mma16816(o[1], ph, vh0[2], vh0[3]);
        mma16816(o[2], ph, vh1[0], vh1[1]);
        mma16816(o[3], ph, vh1[2], vh1[3]);
        mma16816(o[0], pl, vh0[0], vh0[1]);
        mma16816(o[1], pl, vh0[2], vh0[3]);
        mma16816(o[2], pl, vh1[0], vh1[1]);
        mma16816(o[3], pl, vh1[2], vh1[3]);
        mma16816(o[0], ph, vl0[0], vl0[1]);
        mma16816(o[1], ph, vl0[2], vl0[3]);
        mma16816(o[2], ph, vl1[0], vl1[1]);
        mma16816(o[3], ph, vl1[2], vl1[3]);
    }

    #pragma unroll
    for (int vn = 0; vn < 4; vn++) {
        const int col = h * HD + vn * 8 + 2 * (lane & 3);
        if (okA)
            *(float2*)(ctx + ((size_t)b * NTOK + ra) * DIM + col) =
                make_float2(o[vn][0] * invA, o[vn][1] * invA);
        if (okB)
            *(float2*)(ctx + ((size_t)b * NTOK + rb) * DIM + col) =
                make_float2(o[vn][2] * invB, o[vn][3] * invB);
    }
}

// ---------------------------------------------------------------------------
extern "C" void kernel_launch(void* const* d_in, const int* in_sizes, int n_in,
                              void* d_out, int out_size)
{
    const float* skip    = (const float*)d_in[0];
    const float* x_up    = (const float*)d_in[1];
    const float* mask    = (const float*)d_in[2];
    const float* kv_w    = (const float*)d_in[3];
    const float* kv_b    = (const float*)d_in[4];
    const float* proj_w  = (const float*)d_in[5];
    const float* proj_b  = (const float*)d_in[6];
    const float* rpb     = (const float*)d_in[7];
    const int*   rel_idx = (const int*)  d_in[8];
    float* out = (float*)d_out;

    float *kvbuf = nullptr, *ctxbuf = nullptr, *cbbuf = nullptr;
    __nv_bfloat16 *w3kv = nullptr, *w3pj = nullptr;
    cudaGetSymbolAddress((void**)&kvbuf,  g_kv);
    cudaGetSymbolAddress((void**)&ctxbuf, g_ctx);
    cudaGetSymbolAddress((void**)&w3kv,   g_w3kv);
    cudaGetSymbolAddress((void**)&w3pj,   g_w3pj);
    cudaGetSymbolAddress((void**)&cbbuf,  g_cbias);

    const int ATTN_SMEM = 6 * 112 * 40 * 2;   // 53760
    cudaFuncSetAttribute(attn_mma2, cudaFuncAttributeMaxDynamicSharedMemorySize, ATTN_SMEM);

    // #1: kv weight split
    build_w3t<<<(192 * 384 + 255) / 256, 256>>>(kv_w, w3kv, 384);
    // #2: kv = split3(skip) @ w3kv + kv_b
    {
        dim3 grid(384 / 128, MTOT / 128);
        gemm_mma<128><<<grid, 256>>>(skip, w3kv, kv_b, kvbuf, 384);
    }
    // #3: combined bias
    build_cbias<<<(NW * HEADS * NTOK * NTOK + 255) / 256, 256>>>(mask, rpb, rel_idx, cbbuf);
    // #4: attention (profiled slot)
    {
        dim3 grid(HEADS, B_TOT);
        attn_mma2<<<grid, 224, ATTN_SMEM>>>(x_up, kvbuf, cbbuf, ctxbuf);
    }
    // #5: proj weight split
    build_w3t<<<(192 * 192 + 255) / 256, 256>>>(proj_w, w3pj, 192);
    // #6: out = split3(ctx) @ w3pj + proj_b
    {
        dim3 grid(192 / 96, MTOT / 128);
        gemm_mma<96><<<grid, 256>>>(ctxbuf, w3pj, proj_b, out, 192);
    }
}

// round 14
// speedup vs baseline: 1.1137x; 1.0905x over previous
#include <cuda_runtime.h>
#include <cuda_bf16.h>
#include <cuda_fp16.h>
#include <cstdint>
#include <cstddef>

#define B_TOT 1024
#define NTOK  98
#define DIM   192
#define HEADS 6
#define HD    32
#define NW    64
#define TABLE 507
#define MTOT  (B_TOT * NTOK)

__device__ float g_kv [ (size_t)B_TOT * NTOK * 2 * DIM ];
__device__ float g_ctx[ (size_t)B_TOT * NTOK * DIM ];
__device__ __nv_bfloat16 g_w3kv[(size_t)576 * 384];
__device__ __nv_bfloat16 g_w3pj[(size_t)576 * 192];
__device__ __half g_cbias[(size_t)NW * HEADS * NTOK * NTOK];   // fp16: 7.4 MB

// ======================= helpers ===========================================
__device__ __forceinline__ uint32_t smem_u32(const void* p) {
    uint32_t a;
    asm("{ .reg .u64 t; cvta.to.shared.u64 t, %1; cvt.u32.u64 %0, t; }"
        : "=r"(a) : "l"(p));
    return a;
}
__device__ __forceinline__ void ldsm4(uint32_t addr, uint32_t* r) {
    asm volatile("ldmatrix.sync.aligned.m8n8.x4.shared.b16 {%0,%1,%2,%3}, [%4];"
        : "=r"(r[0]), "=r"(r[1]), "=r"(r[2]), "=r"(r[3]) : "r"(addr));
}
__device__ __forceinline__ void ldsm4t(uint32_t addr, uint32_t* r) {
    asm volatile("ldmatrix.sync.aligned.m8n8.x4.trans.shared.b16 {%0,%1,%2,%3}, [%4];"
        : "=r"(r[0]), "=r"(r[1]), "=r"(r[2]), "=r"(r[3]) : "r"(addr));
}
__device__ __forceinline__ void mma16816(float* c, const uint32_t* a,
                                         uint32_t b0, uint32_t b1) {
    asm volatile("mma.sync.aligned.m16n8k16.row.col.f32.bf16.bf16.f32 "
        "{%0,%1,%2,%3}, {%4,%5,%6,%7}, {%8,%9}, {%0,%1,%2,%3};"
        : "+f"(c[0]), "+f"(c[1]), "+f"(c[2]), "+f"(c[3])
        : "r"(a[0]), "r"(a[1]), "r"(a[2]), "r"(a[3]), "r"(b0), "r"(b1));
}
__device__ __forceinline__ uint32_t packbf(float lo, float hi) {
    uint32_t r;
    asm("cvt.rn.bf16x2.f32 %0, %1, %2;" : "=r"(r) : "f"(hi), "f"(lo));
    return r;
}

// ======================= precompute kernels ================================
__global__ void build_w3t(const float* __restrict__ W, __nv_bfloat16* __restrict__ w3t, int N)
{
    int idx = blockIdx.x * 256 + threadIdx.x;
    if (idx >= 192 * N) return;
    int k = idx / N, n = idx % N;
    float a = W[idx];
    __nv_bfloat16 hi = __float2bfloat16_rn(a);
    __nv_bfloat16 lo = __float2bfloat16_rn(a - __bfloat162float(hi));
    w3t[(size_t)k * N + n]         = hi;
    w3t[(size_t)(192 + k) * N + n] = lo;
    w3t[(size_t)(384 + k) * N + n] = hi;
}

__global__ void build_cbias(const float* __restrict__ mask,
                            const float* __restrict__ rpb,
                            const int*   __restrict__ rel_idx,
                            __half* __restrict__ cb)
{
    int idx = blockIdx.x * 256 + threadIdx.x;
    if (idx >= NW * HEADS * NTOK * NTOK) return;
    int k = idx % NTOK;
    int t = idx / NTOK;
    int q = t % NTOK;  t /= NTOK;
    int h = t % HEADS; int w = t / HEADS;
    cb[idx] = __float2half(mask[((size_t)w * NTOK + q) * NTOK + k] +
                           rpb[(size_t)rel_idx[q * NTOK + k] * HEADS + h]);
}

// ======================= R6 mma.sync GEMM (BM=128, measured-good) ==========
template<int BN>
__global__ __launch_bounds__(256) void gemm_mma(
    const float* __restrict__ A,
    const __nv_bfloat16* __restrict__ W3T,   // [576][N]
    const float* __restrict__ bias,
    float* __restrict__ C, int N)
{
    constexpr int SB  = BN + 8;
    constexpr int NFR = BN / 16;
    __shared__ __align__(16) __nv_bfloat16 As[128][72];
    __shared__ __align__(16) __nv_bfloat16 Bs[64][SB];

    const int tid  = threadIdx.x;
    const int lane = tid & 31;
    const int w    = tid >> 5;
    const size_t bm = (size_t)blockIdx.y * 128;
    const int    bn = blockIdx.x * BN;
    const int m0 = (w & 3) * 32, n0 = (w >> 2) * (BN / 2);

    const uint32_t qrow = lane & 15;
    const uint32_t a_base = smem_u32(As) + ((qrow + m0) * 72 + (lane >> 4) * 8) * 2;
    const uint32_t b_base = smem_u32(Bs) + (qrow * SB + n0 + (lane >> 4) * 8) * 2;

    float acc[2][NFR][4] = {};

    const int sched[9] = {0, 3, 1, 4, 2, 5, 6, 7, 8};
    #pragma unroll 1
    for (int s = 0; s < 9; s++) {
        const int c = sched[s];
        const bool newA = !(s == 1 || s == 3 || s == 5);
        __syncthreads();
        if (newA) {
            const int  k0     = (c % 3) * 64;
            const bool use_lo = (c >= 6);
            #pragma unroll
            for (int o = tid; o < 1024; o += 256) {
                int row = o >> 3, cg = (o & 7) * 8;
                const float* ap = &A[(bm + row) * 192 + k0 + cg];
                float4 f0 = *(const float4*)ap;
                float4 f1 = *(const float4*)(ap + 4);
                float v[8] = {f0.x, f0.y, f0.z, f0.w, f1.x, f1.y, f1.z, f1.w};
                union { __nv_bfloat16 hh[8]; uint4 u; } pk;
                #pragma unroll
                for (int i = 0; i < 8; i++) {
                    __nv_bfloat16 hi = __float2bfloat16_rn(v[i]);
                    pk.hh[i] = use_lo ? __float2bfloat16_rn(v[i] - __bfloat162float(hi)) : hi;
                }
                *(uint4*)&As[row][cg] = pk.u;
            }
        }
        #pragma unroll
        for (int o = tid; o < 64 * (BN / 8); o += 256) {
            int kk = o / (BN / 8), cg = (o % (BN / 8)) * 8;
            *(uint4*)&Bs[kk][cg] =
                *(const uint4*)&W3T[(size_t)(c * 64 + kk) * N + bn + cg];
        }
        __syncthreads();

        #pragma unroll
        for (int ks = 0; ks < 4; ks++) {
            uint32_t a[2][4];
            ldsm4(a_base + (uint32_t)(ks * 16 * 2),             a[0]);
            ldsm4(a_base + (uint32_t)((16 * 72 + ks * 16) * 2), a[1]);
            #pragma unroll
            for (int nb = 0; nb < NFR / 2; nb++) {
                uint32_t bq[4];
                ldsm4t(b_base + (uint32_t)((ks * 16 * SB + nb * 16) * 2), bq);
                #pragma unroll
                for (int mi = 0; mi < 2; mi++) {
                    mma16816(acc[mi][2 * nb],     a[mi], bq[0], bq[1]);
                    mma16816(acc[mi][2 * nb + 1], a[mi], bq[2], bq[3]);
                }
            }
        }
    }

    #pragma unroll
    for (int mi = 0; mi < 2; mi++) {
        const size_t row0 = bm + m0 + mi * 16 + (lane >> 2);
        #pragma unroll
        for (int ni = 0; ni < NFR; ni++) {
            const int col = bn + n0 + ni * 8 + 2 * (lane & 3);
            float2 bv = *(const float2*)&bias[col];
            *(float2*)&C[row0 * N + col] =
                make_float2(acc[mi][ni][0] + bv.x, acc[mi][ni][1] + bv.y);
            *(float2*)&C[(row0 + 8) * N + col] =
                make_float2(acc[mi][ni][2] + bv.x, acc[mi][ni][3] + bv.y);
        }
    }
}

// ======================= attention v3.3: occ 3, fp16 cbias =================
__global__ __launch_bounds__(224, 3) void attn_mma2(
    const float* __restrict__ x_up,
    const float* __restrict__ kv,
    const __half* __restrict__ cbias,
    float*       __restrict__ ctx)
{
    const int h = blockIdx.x;
    const int b = blockIdx.y;

    extern __shared__ __align__(16) char smem[];
    __nv_bfloat16* QH = (__nv_bfloat16*)smem;          // [112][40]
    __nv_bfloat16* QL = QH + 112 * 40;
    __nv_bfloat16* KH = QL + 112 * 40;                 // [112][40]
    __nv_bfloat16* KL = KH + 112 * 40;
    __nv_bfloat16* VH = KL + 112 * 40;                 // [112][40]
    __nv_bfloat16* VL = VH + 112 * 40;

    const int tid  = threadIdx.x;
    const int lane = tid & 31;
    const int w    = tid >> 5;
    const float scale = 0.1767766952966369f;

    const float* xb  = x_up + ((size_t)b * NTOK) * DIM + h * HD;
    const float* kvb = kv + (size_t)b * NTOK * 384;

    #pragma unroll
    for (int o = tid; o < 896; o += 224) {
        int row = o >> 3, c4 = (o & 7) * 4;
        uint2 qh = {0, 0}, ql = {0, 0}, kh = {0, 0}, kl = {0, 0}, vh = {0, 0}, vl = {0, 0};
        if (row < NTOK) {
            float4 fq = *(const float4*)(xb + (size_t)row * DIM + c4);
            float4 fk = *(const float4*)(kvb + (size_t)row * 384 + h * HD + c4);
            float4 fv = *(const float4*)(kvb + (size_t)row * 384 + DIM + h * HD + c4);
            float vq[4] = {fq.x * scale, fq.y * scale, fq.z * scale, fq.w * scale};
            float vk[4] = {fk.x, fk.y, fk.z, fk.w};
            float vv[4] = {fv.x, fv.y, fv.z, fv.w};
            union { __nv_bfloat16 h2[4]; uint2 u; } t0, t1;
            #pragma unroll
            for (int i = 0; i < 4; i++) {
                __nv_bfloat16 hi = __float2bfloat16_rn(vq[i]);
                t0.h2[i] = hi;
                t1.h2[i] = __float2bfloat16_rn(vq[i] - __bfloat162float(hi));
            }
            qh = t0.u; ql = t1.u;
            #pragma unroll
            for (int i = 0; i < 4; i++) {
                __nv_bfloat16 hi = __float2bfloat16_rn(vk[i]);
                t0.h2[i] = hi;
                t1.h2[i] = __float2bfloat16_rn(vk[i] - __bfloat162float(hi));
            }
            kh = t0.u; kl = t1.u;
            #pragma unroll
            for (int i = 0; i < 4; i++) {
                __nv_bfloat16 hi = __float2bfloat16_rn(vv[i]);
                t0.h2[i] = hi;
                t1.h2[i] = __float2bfloat16_rn(vv[i] - __bfloat162float(hi));
            }
            vh = t0.u; vl = t1.u;
        }
        *(uint2*)(QH + row * 40 + c4) = qh;
        *(uint2*)(QL + row * 40 + c4) = ql;
        *(uint2*)(KH + row * 40 + c4) = kh;
        *(uint2*)(KL + row * 40 + c4) = kl;
        *(uint2*)(VH + row * 40 + c4) = vh;
        *(uint2*)(VL + row * 40 + c4) = vl;
    }
    __syncthreads();

    const int m0 = w * 16;
    const uint32_t qrow = lane & 15;
    const uint32_t acol = (lane >> 4) * 8;
    const uint32_t aQH = smem_u32(QH) + ((m0 + qrow) * 40 + acol) * 2;
    const uint32_t aQL = aQH + 112 * 40 * 2;
    const uint32_t bKH = smem_u32(KH) + (qrow * 40 + acol) * 2;
    const uint32_t bKL = bKH + 112 * 40 * 2;

    float acc[14][4] = {};
    #pragma unroll
    for (int k16 = 0; k16 < 2; k16++) {
        uint32_t ah[4], al[4];
        ldsm4(aQH + (uint32_t)(k16 * 32), ah);
        ldsm4(aQL + (uint32_t)(k16 * 32), al);
        #pragma unroll
        for (int jt = 0; jt < 7; jt++) {
            uint32_t bh[4], bl[4];
            ldsm4(bKH + (uint32_t)((jt * 16 * 40 + k16 * 16) * 2), bh);
            ldsm4(bKL + (uint32_t)((jt * 16 * 40 + k16 * 16) * 2), bl);
            mma16816(acc[2 * jt],     ah, bh[0], bh[2]);
            mma16816(acc[2 * jt + 1], ah, bh[1], bh[3]);
            mma16816(acc[2 * jt],     al, bh[0], bh[2]);
            mma16816(acc[2 * jt + 1], al, bh[1], bh[3]);
            mma16816(acc[2 * jt],     ah, bl[0], bl[2]);
            mma16816(acc[2 * jt + 1], ah, bl[1], bl[3]);
        }
    }

    const int ra = m0 + (lane >> 2), rb = ra + 8;
    const bool okA = ra < NTOK, okB = rb < NTOK;
    const __half* cbq = cbias + (((size_t)(b & (NW - 1)) * HEADS + h) * NTOK) * NTOK;
    const __half* pA = cbq + (size_t)ra * NTOK;
    const __half* pB = cbq + (size_t)rb * NTOK;
    float sA = 0.f, sB = 0.f;
    #pragma unroll
    for (int ni = 0; ni < 14; ni++) {
        const int c0 = ni * 8 + 2 * (lane & 3);
        const bool okC = c0 < NTOK;
        float e0 = 0.f, e1 = 0.f, e2 = 0.f, e3 = 0.f;
        if (okA && okC) {
            float2 cb = __half22float2(*(const __half2*)(pA + c0));
            e0 = __expf(acc[ni][0] + cb.x);
            e1 = __expf(acc[ni][1] + cb.y);
        }
        if (okB && okC) {
            float2 cb = __half22float2(*(const __half2*)(pB + c0));
            e2 = __expf(acc[ni][2] + cb.x);
            e3 = __expf(acc[ni][3] + cb.y);
        }
        sA += e0 + e1; sB += e2 + e3;
        acc[ni][0] = e0; acc[ni][1] = e1;
        acc[ni][2] = e2; acc[ni][3] = e3;
    }
    sA += __shfl_xor_sync(0xffffffffu, sA, 1);
    sA += __shfl_xor_sync(0xffffffffu, sA, 2);
    sB += __shfl_xor_sync(0xffffffffu, sB, 1);
    sB += __shfl_xor_sync(0xffffffffu, sB, 2);
    const float invA = 1.f / sA, invB = 1.f / sB;

    float o[4][4] = {};
    const uint32_t bVH = smem_u32(VH) + (qrow * 40 + acol) * 2;
    const uint32_t bVL = bVH + 112 * 40 * 2;
    #pragma unroll
    for (int kt = 0; kt < 7; kt++) {
        const float* cA = acc[2 * kt];
        const float* cB = acc[2 * kt + 1];
        uint32_t ph[4], pl[4];
        ph[0] = packbf(cA[0], cA[1]);
        ph[1] = packbf(cA[2], cA[3]);
        ph[2] = packbf(cB[0], cB[1]);
        ph[3] = packbf(cB[2], cB[3]);
        pl[0] = packbf(cA[0] - __uint_as_float(ph[0] << 16),
                       cA[1] - __uint_as_float(ph[0] & 0xFFFF0000u));
        pl[1] = packbf(cA[2] - __uint_as_float(ph[1] << 16),
                       cA[3] - __uint_as_float(ph[1] & 0xFFFF0000u));
        pl[2] = packbf(cB[0] - __uint_as_float(ph[2] << 16),
                       cB[1] - __uint_as_float(ph[2] & 0xFFFF0000u));
        pl[3] = packbf(cB[2] - __uint_as_float(ph[3] << 16),
                       cB[3] - __uint_as_float(ph[3] & 0xFFFF0000u));

        uint32_t vh0[4], vh1[4], vl0[4], vl1[4];
        ldsm4t(bVH + (uint32_t)(kt * 16 * 40 * 2),        vh0);
        ldsm4t(bVH + (uint32_t)((kt * 16 * 40 + 16) * 2), vh1);
        ldsm4t(bVL + (uint32_t)(kt * 16 * 40 * 2),        vl0);
        ldsm4t(bVL + (uint32_t)((kt * 16 * 40 + 16) * 2), vl1);

        mma16816(o[0], ph, vh0[0], vh0[1]);
        mma16816(o[1], ph, vh0[2], vh0[3]);
        mma16816(o[2], ph, vh1[0], vh1[1]);
        mma16816(o[3], ph, vh1[2], vh1[3]);
        mma16816(o[0], pl, vh0[0], vh0[1]);
        mma16816(o[1], pl, vh0[2], vh0[3]);
        mma16816(o[2], pl, vh1[0], vh1[1]);
        mma16816(o[3], pl, vh1[2], vh1[3]);
        mma16816(o[0], ph, vl0[0], vl0[1]);
        mma16816(o[1], ph, vl0[2], vl0[3]);
        mma16816(o[2], ph, vl1[0], vl1[1]);
        mma16816(o[3], ph, vl1[2], vl1[3]);
    }

    #pragma unroll
    for (int vn = 0; vn < 4; vn++) {
        const int col = h * HD + vn * 8 + 2 * (lane & 3);
        if (okA)
            *(float2*)(ctx + ((size_t)b * NTOK + ra) * DIM + col) =
                make_float2(o[vn][0] * invA, o[vn][1] * invA);
        if (okB)
            *(float2*)(ctx + ((size_t)b * NTOK + rb) * DIM + col) =
                make_float2(o[vn][2] * invB, o[vn][3] * invB);
    }
}

// ---------------------------------------------------------------------------
extern "C" void kernel_launch(void* const* d_in, const int* in_sizes, int n_in,
                              void* d_out, int out_size)
{
    const float* skip    = (const float*)d_in[0];
    const float* x_up    = (const float*)d_in[1];
    const float* mask    = (const float*)d_in[2];
    const float* kv_w    = (const float*)d_in[3];
    const float* kv_b    = (const float*)d_in[4];
    const float* proj_w  = (const float*)d_in[5];
    const float* proj_b  = (const float*)d_in[6];
    const float* rpb     = (const float*)d_in[7];
    const int*   rel_idx = (const int*)  d_in[8];
    float* out = (float*)d_out;

    float *kvbuf = nullptr, *ctxbuf = nullptr;
    __half* cbbuf = nullptr;
    __nv_bfloat16 *w3kv = nullptr, *w3pj = nullptr;
    cudaGetSymbolAddress((void**)&kvbuf,  g_kv);
    cudaGetSymbolAddress((void**)&ctxbuf, g_ctx);
    cudaGetSymbolAddress((void**)&w3kv,   g_w3kv);
    cudaGetSymbolAddress((void**)&w3pj,   g_w3pj);
    cudaGetSymbolAddress((void**)&cbbuf,  g_cbias);

    const int ATTN_SMEM = 6 * 112 * 40 * 2;   // 53760
    cudaFuncSetAttribute(attn_mma2, cudaFuncAttributeMaxDynamicSharedMemorySize, ATTN_SMEM);

    // #1: kv weight split
    build_w3t<<<(192 * 384 + 255) / 256, 256>>>(kv_w, w3kv, 384);
    // #2: kv = split3(skip) @ w3kv + kv_b
    {
        dim3 grid(384 / 128, MTOT / 128);
        gemm_mma<128><<<grid, 256>>>(skip, w3kv, kv_b, kvbuf, 384);
    }
    // #3: combined bias (fp16)
    build_cbias<<<(NW * HEADS * NTOK * NTOK + 255) / 256, 256>>>(mask, rpb, rel_idx, cbbuf);
    // #4: attention (profiled slot)
    {
        dim3 grid(HEADS, B_TOT);
        attn_mma2<<<grid, 224, ATTN_SMEM>>>(x_up, kvbuf, cbbuf, ctxbuf);
    }
    // #5: proj weight split
    build_w3t<<<(192 * 192 + 255) / 256, 256>>>(proj_w, w3pj, 192);
    // #6: out = split3(ctx) @ w3pj + proj_b
    {
        dim3 grid(192 / 96, MTOT / 128);
        gemm_mma<96><<<grid, 256>>>(ctxbuf, w3pj, proj_b, out, 192);
    }
}